// round 7
// baseline (speedup 1.0000x reference)
#include <cuda_runtime.h>
#include <cuda_bf16.h>
#include <cfloat>
#include <cstdint>

// ---------------------------------------------------------------------------
// RetinaNet postprocess, round 7: four kernels.
//   prep  (grid)   : coalesced float4 class-max (SMEM atomicMax), decode+clip,
//                    direct slab emit (score > CUTOFF, compile-time cut)
//   nms1  (1 block): rank slab -> pairwise IoU masks in SMEM -> 1-warp exact
//                    greedy -> publish kept snapshot; reset counters
//   flag  (grid)   : tail candidates vs snapshot kept set (early-exit IoU);
//                    survivors appended unordered
//   nms2  (1 block): reference argmax+suppress greedy over survivors (exact),
//                    then per-keep class argmax + output tuple
// Exactness: slab = {score > CUTOFF} is a clean cut in descending (score,idx)
// order; kept set monotone => snapshot suppression is final; survivors are
// re-processed in exact sorted order. Slab overflow (>T0) falls back to
// slab=empty: all work flows through the exact tail path (slow but correct).
// ---------------------------------------------------------------------------

#define MAXA   262144
#define MAXDET 300
#define T0     1024
#define W0     16
#define PSTTHD 0.05f
#define CUTOFF 0.99995f
#define NMSTHD 0.5f

typedef unsigned long long ull;

__device__ float  g_keys [MAXA];
__device__ float4 g_boxes[MAXA];
__device__ float  g_areas[MAXA];
__device__ ull    g_ckeys[T0];
__device__ ull    g_skey [MAXA];
__device__ float4 g_kbox [MAXDET];
__device__ float  g_karea[MAXDET];
__device__ int    g_keep [MAXDET];
__device__ int    g_scnt;
__device__ int    g_nsurv;
__device__ int    g_nk;
__device__ int    g_overflow;

__device__ __forceinline__ bool sup_test(float x1, float y1, float x2, float y2, float ar,
                                         float X1, float Y1, float X2, float Y2, float AR)
{
    float xx1 = fmaxf(x1, X1);
    float yy1 = fmaxf(y1, Y1);
    float xx2 = fminf(x2, X2);
    float yy2 = fminf(y2, Y2);
    float inter = fmaxf(xx2 - xx1, 0.0f) * fmaxf(yy2 - yy1, 0.0f);
    float iou = inter / (ar + AR - inter + 1e-8f);
    return iou > NMSTHD;
}

// ---------------------------------------------------------------------------
// prep: 64 anchors per 256-thread block; flat float4 streaming + SMEM
// atomicMax per row (scores >= 0 so uint order == float order).
// ---------------------------------------------------------------------------
__global__ void prep_kernel(const float* __restrict__ cls,
                            const float* __restrict__ reg,
                            const float* __restrict__ anc,
                            const int*   __restrict__ ph,
                            const int*   __restrict__ pw,
                            int A, int C)
{
    __shared__ unsigned srow[64];
    int t = threadIdx.x;
    int base = blockIdx.x * 64;
    if (t < 64) srow[t] = 0u;
    __syncthreads();

    if ((C & 3) == 0) {
        int f4r = C >> 2;
        int tot = 64 * f4r;
        const float4* cb = (const float4*)cls + (size_t)base * f4r;
        for (int i = t; i < tot; i += blockDim.x) {
            int r = i / f4r;
            if (base + r < A) {
                float4 v = cb[i];
                float m = fmaxf(fmaxf(v.x, v.y), fmaxf(v.z, v.w));
                atomicMax(&srow[r], __float_as_uint(m));
            }
        }
    } else {
        for (int i = t; i < 64 * C; i += blockDim.x) {
            int r = i / C;
            if (base + r < A) {
                float m = cls[(size_t)(base + r) * C + (i % C)];
                atomicMax(&srow[r], __float_as_uint(m));
            }
        }
    }
    __syncthreads();

    if (t < 64) {
        int a = base + t;
        if (a < A) {
            float m = __uint_as_float(srow[t]);
            g_keys[a] = (m > PSTTHD) ? m : 0.0f;
            if (m > CUTOFF) {
                int p = atomicAdd(&g_scnt, 1);
                if (p < T0)
                    g_ckeys[p] = ((ull)__float_as_uint(m) << 18) |
                                 (ull)(0x3FFFFu - (unsigned)a);
            }

            float4 an = ((const float4*)anc)[a];
            float4 rg = ((const float4*)reg)[a];
            float bw = an.z - an.x;
            float bh = an.w - an.y;
            float cx = an.x + 0.5f * bw;
            float cy = an.y + 0.5f * bh;
            float pcx = cx + (rg.x * 0.1f) * bw;
            float pcy = cy + (rg.y * 0.1f) * bh;
            float pw_ = expf(rg.z * 0.2f) * bw;
            float ph_ = expf(rg.w * 0.2f) * bh;

            float W = pw ? (float)__ldg(pw) : 1024.0f;
            float H = ph ? (float)__ldg(ph) : 1024.0f;

            float x1 = fmaxf(pcx - 0.5f * pw_, 0.0f);
            float y1 = fmaxf(pcy - 0.5f * ph_, 0.0f);
            float x2 = fminf(pcx + 0.5f * pw_, W);
            float y2 = fminf(pcy + 0.5f * ph_, H);

            g_boxes[a] = make_float4(x1, y1, x2, y2);
            g_areas[a] = (x2 - x1) * (y2 - y1);
        }
    }
}

// ---------------------------------------------------------------------------
// nms1: one block. Rank slab, build pairwise masks in SMEM, 1-warp exact
// greedy, publish kept snapshot. Resets g_scnt / g_nsurv for the pipeline.
// ---------------------------------------------------------------------------
__global__ void __launch_bounds__(1024, 1)
nms1_kernel()
{
    extern __shared__ ull smasks[];           // T0*W0 = 128 KB
    __shared__ ull    skeys[T0];
    __shared__ int    sidx [T0];
    __shared__ float4 scb  [T0];
    __shared__ float  sca  [T0];
    __shared__ int    spos [MAXDET];
    __shared__ int    s_nk;

    int t = threadIdx.x;
    int scnt = g_scnt;
    int overflow = (scnt > T0) ? 1 : 0;
    int n = overflow ? 0 : scnt;

    skeys[t] = (t < n) ? g_ckeys[t] : 0ULL;
    if (t == 0) s_nk = 0;
    __syncthreads();

    if (t < n) {
        ull mykey = skeys[t];
        int r = 0;
        for (int j = 0; j < n; j++) r += (skeys[j] > mykey) ? 1 : 0;
        int a = (int)(0x3FFFFu - (unsigned)(mykey & 0x3FFFFULL));
        sidx[r] = a;
        scb[r]  = g_boxes[a];
        sca[r]  = g_areas[a];
    }
    __syncthreads();

    int items = n * W0;
    for (int it = t; it < items; it += 1024) {
        int i = it >> 4;
        int w = it & 15;
        int jbase = w << 6;
        ull word = 0ULL;
        if (jbase < i) {
            float4 bi = scb[i];
            float  ai = sca[i];
            int jend = min(jbase + 64, i);
            for (int j = jbase; j < jend; j++) {
                float4 bj = scb[j];
                if (sup_test(bi.x, bi.y, bi.z, bi.w, ai,
                             bj.x, bj.y, bj.z, bj.w, sca[j]))
                    word |= 1ULL << (j - jbase);
            }
        }
        smasks[it] = word;
    }
    __syncthreads();

    if (t < 32) {
        int lane = t;
        ull kept = 0ULL;
        int nk = 0;
        ull nrow = (n > 0 && lane < W0) ? smasks[lane] : 0ULL;
        for (int i = 0; i < n; i++) {
            ull row = nrow;
            nrow = (i + 1 < n && lane < W0) ? smasks[(i + 1) * W0 + lane] : 0ULL;
            bool hit = (row & kept) != 0ULL;
            if (!__any_sync(0xffffffffu, hit)) {
                if (lane == (i >> 6)) kept |= 1ULL << (i & 63);
                if (lane == 0) spos[nk] = i;
                nk++;
                if (nk >= MAXDET) break;
            }
        }
        if (lane == 0) s_nk = nk;
    }
    __syncthreads();

    int nk = s_nk;
    for (int k = t; k < nk; k += 1024) {
        int p = spos[k];
        g_keep[k]  = sidx[p];
        g_kbox[k]  = scb[p];
        g_karea[k] = sca[p];
    }
    if (t == 0) {
        g_nk = nk;
        g_overflow = overflow;
        g_scnt = 0;                           // ready for next replay
        g_nsurv = 0;                          // ready for flag kernel
    }
}

// ---------------------------------------------------------------------------
// flag: grid-wide tail suppression vs snapshot kept set; append survivors.
// ---------------------------------------------------------------------------
__global__ void flag_kernel(int A)
{
    __shared__ float4 skb[MAXDET];
    __shared__ float  ska[MAXDET];
    __shared__ int    snk, sovf;
    if (threadIdx.x == 0) { snk = g_nk; sovf = g_overflow; }
    __syncthreads();
    int nk = snk;
    if (nk >= MAXDET) return;
    for (int k = threadIdx.x; k < nk; k += blockDim.x) {
        skb[k] = g_kbox[k];
        ska[k] = g_karea[k];
    }
    __syncthreads();

    int a = blockIdx.x * blockDim.x + threadIdx.x;
    if (a >= A) return;
    float key = g_keys[a];
    if (!(key > PSTTHD)) return;
    if (!sovf && key > CUTOFF) return;        // slab member, already processed

    float4 b = g_boxes[a];
    float ar = g_areas[a];
    for (int k = 0; k < nk; k++) {
        if (sup_test(b.x, b.y, b.z, b.w, ar,
                     skb[k].x, skb[k].y, skb[k].z, skb[k].w, ska[k]))
            return;
    }
    int p = atomicAdd(&g_nsurv, 1);
    g_skey[p] = ((ull)__float_as_uint(key) << 18) |
                (ull)(0x3FFFFu - (unsigned)a);
}

// ---------------------------------------------------------------------------
// nms2: one block. Reference argmax+suppress greedy over survivors, then
// final per-keep class argmax + output tuple.
// ---------------------------------------------------------------------------
__global__ void __launch_bounds__(1024, 1)
nms2_kernel(const float* __restrict__ cls, int C, float* __restrict__ out)
{
    __shared__ ull    sb[1024];
    __shared__ float4 swin;
    __shared__ float  swar;
    int t = threadIdx.x;
    int nk = g_nk;
    int ns = g_nsurv;

    while (nk < MAXDET && ns > 0) {
        ull best = 0ULL;
        for (int i = t; i < ns; i += 1024) {
            ull v = g_skey[i];
            if (v > best) best = v;
        }
        sb[t] = best;
        __syncthreads();
        for (int off = 512; off; off >>= 1) {
            if (t < off && sb[t + off] > sb[t]) sb[t] = sb[t + off];
            __syncthreads();
        }
        if (sb[0] == 0ULL) break;

        if (t == 0) {
            int a = (int)(0x3FFFFu - (unsigned)(sb[0] & 0x3FFFFULL));
            float4 b = g_boxes[a];
            float ar = g_areas[a];
            g_keep[nk]  = a;
            g_kbox[nk]  = b;
            g_karea[nk] = ar;
            swin = b;
            swar = ar;
        }
        __syncthreads();
        float4 wb = swin;
        float war = swar;
        for (int i = t; i < ns; i += 1024) {
            ull v = g_skey[i];
            if (v != 0ULL) {
                int a = (int)(0x3FFFFu - (unsigned)(v & 0x3FFFFULL));
                float4 b = g_boxes[a];
                if (sup_test(b.x, b.y, b.z, b.w, g_areas[a],
                             wb.x, wb.y, wb.z, wb.w, war))
                    g_skey[i] = 0ULL;          // winner self-suppresses too
            }
        }
        nk++;
        __syncthreads();
    }
    __syncthreads();

    // ---- final: warp per keep slot ----
    int warp = t >> 5;
    int lane = t & 31;
    for (int d = warp; d < MAXDET; d += 32) {
        bool valid = d < nk;
        float score = 0.f, clsid = -1.f;
        float bx0 = 0.f, bx1 = 0.f, bx2 = 0.f, bx3 = 0.f;
        if (valid) {
            int idx = g_keep[d];
            const float* row = cls + (size_t)idx * C;
            float best = -FLT_MAX;
            int bi = 0x7fffffff;
            for (int c = lane; c < C; c += 32) {
                float vv = row[c];
                if (vv > best) { best = vv; bi = c; }
            }
            #pragma unroll
            for (int off = 16; off; off >>= 1) {
                float ov = __shfl_down_sync(0xffffffffu, best, off);
                int   oi = __shfl_down_sync(0xffffffffu, bi,   off);
                if (ov > best || (ov == best && oi < bi)) { best = ov; bi = oi; }
            }
            best = __shfl_sync(0xffffffffu, best, 0);
            bi   = __shfl_sync(0xffffffffu, bi,   0);
            score = best;
            clsid = (float)bi;
            float4 b = g_kbox[d];
            bx0 = b.x; bx1 = b.y; bx2 = b.z; bx3 = b.w;
        }
        if (lane == 0) {
            out[d]                      = score;
            out[MAXDET + d]             = clsid;
            out[2 * MAXDET + 4 * d + 0] = bx0;
            out[2 * MAXDET + 4 * d + 1] = bx1;
            out[2 * MAXDET + 4 * d + 2] = bx2;
            out[2 * MAXDET + 4 * d + 3] = bx3;
            out[6 * MAXDET + d]         = valid ? 1.0f : 0.0f;
        }
    }
}

// ---------------------------------------------------------------------------
extern "C" void kernel_launch(void* const* d_in, const int* in_sizes, int n_in,
                              void* d_out, int out_size)
{
    const float* cls = (const float*)d_in[0];
    const float* reg = (const float*)d_in[1];
    const float* anc = (const float*)d_in[2];
    const int*   ph  = (n_in > 3) ? (const int*)d_in[3] : nullptr;
    const int*   pw  = (n_in > 4) ? (const int*)d_in[4] : nullptr;

    int A = in_sizes[2] / 4;
    if (A > MAXA) A = MAXA;
    int C = in_sizes[0] / A;

    cudaFuncSetAttribute(nms1_kernel,
                         cudaFuncAttributeMaxDynamicSharedMemorySize,
                         T0 * W0 * (int)sizeof(ull));

    prep_kernel<<<(A + 63) / 64, 256>>>(cls, reg, anc, ph, pw, A, C);
    nms1_kernel<<<1, 1024, T0 * W0 * sizeof(ull)>>>();
    flag_kernel<<<(A + 255) / 256, 256>>>(A);
    nms2_kernel<<<1, 1024>>>(cls, C, (float*)d_out);
}

// round 8
// speedup vs baseline: 3.7856x; 3.7856x over previous
#include <cuda_runtime.h>
#include <cuda_bf16.h>
#include <cfloat>
#include <cstdint>

// ---------------------------------------------------------------------------
// RetinaNet postprocess, round 8: five kernels.
//   prep  (grid)    : coalesced float4 class-max (SMEM atomicMax), decode+clip,
//                     direct slab emit (score > CUTOFF compile-time cut)
//   pair  (64 blks) : each block ranks the slab in SMEM (redundant, parallel),
//                     computes its slice of pairwise IoU masks -> global;
//                     block 0 publishes sorted compact arrays
//   scan0 (1 warp)  : exact greedy over slab via double-buffered mask rows;
//                     publishes kept set; resets counters
//   flag  (grid)    : tail candidates vs snapshot kept set (early-exit at
//                     nk==300); survivors appended unordered
//   nms2  (1 block) : reference argmax+suppress greedy over survivors (exact,
//                     normally empty) + per-keep class argmax + output tuple
// Exactness: slab = {score > CUTOFF} is a clean cut in descending (score,idx)
// order; kept set monotone => snapshot suppression final; survivors re-done in
// exact sorted order. Slab overflow (>T0, ~8-sigma) => slab treated empty, all
// work flows through the exact tail path (slow but correct).
// ---------------------------------------------------------------------------

#define MAXA   262144
#define MAXDET 300
#define T0     1024
#define W0     16
#define PAIRB  64
#define PSTTHD 0.05f
#define CUTOFF 0.99995f
#define NMSTHD 0.5f

typedef unsigned long long ull;

__device__ float  g_keys [MAXA];
__device__ float4 g_boxes[MAXA];
__device__ float  g_areas[MAXA];
__device__ ull    g_ckeys[T0];
__device__ int    g_cidx [T0];
__device__ float4 g_cbox [T0];
__device__ float  g_carea[T0];
__device__ ull    g_mask [T0 * W0];
__device__ ull    g_skey [MAXA];
__device__ float4 g_kbox [MAXDET];
__device__ float  g_karea[MAXDET];
__device__ int    g_keep [MAXDET];
__device__ int    g_scnt;
__device__ int    g_nsurv;
__device__ int    g_nk;
__device__ int    g_overflow;

__device__ __forceinline__ bool sup_test(float x1, float y1, float x2, float y2, float ar,
                                         float X1, float Y1, float X2, float Y2, float AR)
{
    float xx1 = fmaxf(x1, X1);
    float yy1 = fmaxf(y1, Y1);
    float xx2 = fminf(x2, X2);
    float yy2 = fminf(y2, Y2);
    float inter = fmaxf(xx2 - xx1, 0.0f) * fmaxf(yy2 - yy1, 0.0f);
    float iou = inter / (ar + AR - inter + 1e-8f);
    return iou > NMSTHD;
}

// ---------------------------------------------------------------------------
// prep: 64 anchors per 256-thread block; flat float4 streaming + SMEM
// atomicMax per row (scores >= 0 so uint order == float order).
// ---------------------------------------------------------------------------
__global__ void prep_kernel(const float* __restrict__ cls,
                            const float* __restrict__ reg,
                            const float* __restrict__ anc,
                            const int*   __restrict__ ph,
                            const int*   __restrict__ pw,
                            int A, int C)
{
    __shared__ unsigned srow[64];
    int t = threadIdx.x;
    int base = blockIdx.x * 64;
    if (t < 64) srow[t] = 0u;
    __syncthreads();

    if ((C & 3) == 0) {
        int f4r = C >> 2;
        int tot = 64 * f4r;
        const float4* cb = (const float4*)cls + (size_t)base * f4r;
        for (int i = t; i < tot; i += blockDim.x) {
            int r = i / f4r;
            if (base + r < A) {
                float4 v = cb[i];
                float m = fmaxf(fmaxf(v.x, v.y), fmaxf(v.z, v.w));
                atomicMax(&srow[r], __float_as_uint(m));
            }
        }
    } else {
        for (int i = t; i < 64 * C; i += blockDim.x) {
            int r = i / C;
            if (base + r < A) {
                float m = cls[(size_t)(base + r) * C + (i % C)];
                atomicMax(&srow[r], __float_as_uint(m));
            }
        }
    }
    __syncthreads();

    if (t < 64) {
        int a = base + t;
        if (a < A) {
            float m = __uint_as_float(srow[t]);
            g_keys[a] = (m > PSTTHD) ? m : 0.0f;
            if (m > CUTOFF) {
                int p = atomicAdd(&g_scnt, 1);
                if (p < T0)
                    g_ckeys[p] = ((ull)__float_as_uint(m) << 18) |
                                 (ull)(0x3FFFFu - (unsigned)a);
            }

            float4 an = ((const float4*)anc)[a];
            float4 rg = ((const float4*)reg)[a];
            float bw = an.z - an.x;
            float bh = an.w - an.y;
            float cx = an.x + 0.5f * bw;
            float cy = an.y + 0.5f * bh;
            float pcx = cx + (rg.x * 0.1f) * bw;
            float pcy = cy + (rg.y * 0.1f) * bh;
            float pw_ = expf(rg.z * 0.2f) * bw;
            float ph_ = expf(rg.w * 0.2f) * bh;

            float W = pw ? (float)__ldg(pw) : 1024.0f;
            float H = ph ? (float)__ldg(ph) : 1024.0f;

            float x1 = fmaxf(pcx - 0.5f * pw_, 0.0f);
            float y1 = fmaxf(pcy - 0.5f * ph_, 0.0f);
            float x2 = fminf(pcx + 0.5f * pw_, W);
            float y2 = fminf(pcy + 0.5f * ph_, H);

            g_boxes[a] = make_float4(x1, y1, x2, y2);
            g_areas[a] = (x2 - x1) * (y2 - y1);
        }
    }
}

// ---------------------------------------------------------------------------
// pair: PAIRB blocks x 256. Each block redundantly ranks the slab into SMEM
// (keys unique => deterministic), then computes its strided slice of pairwise
// suppression mask words. Block 0 also publishes the sorted compact arrays.
// ---------------------------------------------------------------------------
__global__ void __launch_bounds__(256, 4)
pair_kernel()
{
    __shared__ ull    skeys[T0];
    __shared__ float4 scb  [T0];
    __shared__ float  sca  [T0];
    __shared__ int    sidx [T0];

    int t = threadIdx.x;
    int scnt = g_scnt;
    int n = (scnt > T0) ? 0 : scnt;
    if (n == 0) return;

    for (int i = t; i < n; i += 256) skeys[i] = g_ckeys[i];
    __syncthreads();

    // rank by comparison (broadcast SMEM reads; all lanes share j)
    for (int i = t; i < n; i += 256) {
        ull mykey = skeys[i];
        int r = 0;
        for (int j = 0; j < n; j++) r += (skeys[j] > mykey) ? 1 : 0;
        int a = (int)(0x3FFFFu - (unsigned)(mykey & 0x3FFFFULL));
        sidx[r] = a;
        scb[r]  = g_boxes[a];
        sca[r]  = g_areas[a];
    }
    __syncthreads();

    if (blockIdx.x == 0) {
        for (int i = t; i < n; i += 256) {
            g_cidx[i]  = sidx[i];
            g_cbox[i]  = scb[i];
            g_carea[i] = sca[i];
        }
    }

    int items = n * W0;
    for (int it = blockIdx.x * 256 + t; it < items; it += PAIRB * 256) {
        int i = it >> 4;
        int w = it & 15;
        int jbase = w << 6;
        ull word = 0ULL;
        if (jbase < i) {
            float4 bi = scb[i];
            float  ai = sca[i];
            int jend = min(jbase + 64, i);
            for (int j = jbase; j < jend; j++) {
                float4 bj = scb[j];
                if (sup_test(bi.x, bi.y, bi.z, bi.w, ai,
                             bj.x, bj.y, bj.z, bj.w, sca[j]))
                    word |= 1ULL << (j - jbase);
            }
        }
        g_mask[it] = word;
    }
}

// ---------------------------------------------------------------------------
// scan0: 1 warp. Exact greedy over slab, double-buffered 16-row prefetch of
// mask rows from global. Publishes kept set; resets counters for next replay.
// ---------------------------------------------------------------------------
__device__ __forceinline__ void load_chunk(ull (&b)[16], int base, int n, int lane)
{
    #pragma unroll
    for (int r = 0; r < 16; r++) {
        int i = base + r;
        b[r] = (i < n && lane < W0) ? g_mask[(size_t)i * W0 + lane] : 0ULL;
    }
}

__global__ void scan0_kernel()
{
    __shared__ int spos[MAXDET];
    int lane = threadIdx.x;
    int scnt = g_scnt;
    int overflow = (scnt > T0) ? 1 : 0;
    int n = overflow ? 0 : scnt;

    ull kept = 0ULL;
    int nk = 0;
    bool done = (n == 0);

    ull bufA[16], bufB[16];
    load_chunk(bufA, 0, n, lane);

    for (int base = 0; base < n && !done; base += 32) {
        load_chunk(bufB, base + 16, n, lane);
        #pragma unroll
        for (int r = 0; r < 16; r++) {
            int i = base + r;
            if (i >= n) { done = true; break; }
            bool hit = (bufA[r] & kept) != 0ULL;
            if (!__any_sync(0xffffffffu, hit)) {
                if (lane == (i >> 6)) kept |= 1ULL << (i & 63);
                if (lane == 0) spos[nk] = i;
                nk++;
                if (nk >= MAXDET) { done = true; break; }
            }
        }
        if (done) break;
        load_chunk(bufA, base + 32, n, lane);
        #pragma unroll
        for (int r = 0; r < 16; r++) {
            int i = base + 16 + r;
            if (i >= n) { done = true; break; }
            bool hit = (bufB[r] & kept) != 0ULL;
            if (!__any_sync(0xffffffffu, hit)) {
                if (lane == (i >> 6)) kept |= 1ULL << (i & 63);
                if (lane == 0) spos[nk] = i;
                nk++;
                if (nk >= MAXDET) { done = true; break; }
            }
        }
    }

    __syncwarp();
    for (int k = lane; k < nk; k += 32) {         // nk warp-uniform
        int p = spos[k];
        g_keep[k]  = g_cidx[p];
        g_kbox[k]  = g_cbox[p];
        g_karea[k] = g_carea[p];
    }
    if (lane == 0) {
        g_nk = nk;
        g_overflow = overflow;
        g_scnt = 0;                               // ready for next replay
        g_nsurv = 0;
    }
}

// ---------------------------------------------------------------------------
// flag: grid-wide tail suppression vs snapshot kept set; append survivors.
// Early-exits when the slab already yielded 300 keeps.
// ---------------------------------------------------------------------------
__global__ void flag_kernel(int A)
{
    __shared__ float4 skb[MAXDET];
    __shared__ float  ska[MAXDET];
    __shared__ int    snk, sovf;
    if (threadIdx.x == 0) { snk = g_nk; sovf = g_overflow; }
    __syncthreads();
    int nk = snk;
    if (nk >= MAXDET) return;
    for (int k = threadIdx.x; k < nk; k += blockDim.x) {
        skb[k] = g_kbox[k];
        ska[k] = g_karea[k];
    }
    __syncthreads();

    int a = blockIdx.x * blockDim.x + threadIdx.x;
    if (a >= A) return;
    float key = g_keys[a];
    if (!(key > PSTTHD)) return;
    if (!sovf && key > CUTOFF) return;            // slab member, already done

    float4 b = g_boxes[a];
    float ar = g_areas[a];
    for (int k = 0; k < nk; k++) {
        if (sup_test(b.x, b.y, b.z, b.w, ar,
                     skb[k].x, skb[k].y, skb[k].z, skb[k].w, ska[k]))
            return;
    }
    int p = atomicAdd(&g_nsurv, 1);
    g_skey[p] = ((ull)__float_as_uint(key) << 18) |
                (ull)(0x3FFFFu - (unsigned)a);
}

// ---------------------------------------------------------------------------
// nms2: serial reference greedy over survivors (normally none) + final output.
// ---------------------------------------------------------------------------
__global__ void __launch_bounds__(1024, 1)
nms2_kernel(const float* __restrict__ cls, int C, float* __restrict__ out)
{
    __shared__ ull    sb[1024];
    __shared__ float4 swin;
    __shared__ float  swar;
    int t = threadIdx.x;
    int nk = g_nk;
    int ns = g_nsurv;

    while (nk < MAXDET && ns > 0) {
        ull best = 0ULL;
        for (int i = t; i < ns; i += 1024) {
            ull v = g_skey[i];
            if (v > best) best = v;
        }
        sb[t] = best;
        __syncthreads();
        for (int off = 512; off; off >>= 1) {
            if (t < off && sb[t + off] > sb[t]) sb[t] = sb[t + off];
            __syncthreads();
        }
        if (sb[0] == 0ULL) break;

        if (t == 0) {
            int a = (int)(0x3FFFFu - (unsigned)(sb[0] & 0x3FFFFULL));
            float4 b = g_boxes[a];
            float ar = g_areas[a];
            g_keep[nk]  = a;
            g_kbox[nk]  = b;
            g_karea[nk] = ar;
            swin = b;
            swar = ar;
        }
        __syncthreads();
        float4 wb = swin;
        float war = swar;
        for (int i = t; i < ns; i += 1024) {
            ull v = g_skey[i];
            if (v != 0ULL) {
                int a = (int)(0x3FFFFu - (unsigned)(v & 0x3FFFFULL));
                float4 b = g_boxes[a];
                if (sup_test(b.x, b.y, b.z, b.w, g_areas[a],
                             wb.x, wb.y, wb.z, wb.w, war))
                    g_skey[i] = 0ULL;              // winner self-suppresses too
            }
        }
        nk++;
        __syncthreads();
    }
    __syncthreads();

    int warp = t >> 5;
    int lane = t & 31;
    for (int d = warp; d < MAXDET; d += 32) {
        bool valid = d < nk;
        float score = 0.f, clsid = -1.f;
        float bx0 = 0.f, bx1 = 0.f, bx2 = 0.f, bx3 = 0.f;
        if (valid) {
            int idx = g_keep[d];
            const float* row = cls + (size_t)idx * C;
            float best = -FLT_MAX;
            int bi = 0x7fffffff;
            for (int c = lane; c < C; c += 32) {
                float vv = row[c];
                if (vv > best) { best = vv; bi = c; }
            }
            #pragma unroll
            for (int off = 16; off; off >>= 1) {
                float ov = __shfl_down_sync(0xffffffffu, best, off);
                int   oi = __shfl_down_sync(0xffffffffu, bi,   off);
                if (ov > best || (ov == best && oi < bi)) { best = ov; bi = oi; }
            }
            best = __shfl_sync(0xffffffffu, best, 0);
            bi   = __shfl_sync(0xffffffffu, bi,   0);
            score = best;
            clsid = (float)bi;
            float4 b = g_kbox[d];
            bx0 = b.x; bx1 = b.y; bx2 = b.z; bx3 = b.w;
        }
        if (lane == 0) {
            out[d]                      = score;
            out[MAXDET + d]             = clsid;
            out[2 * MAXDET + 4 * d + 0] = bx0;
            out[2 * MAXDET + 4 * d + 1] = bx1;
            out[2 * MAXDET + 4 * d + 2] = bx2;
            out[2 * MAXDET + 4 * d + 3] = bx3;
            out[6 * MAXDET + d]         = valid ? 1.0f : 0.0f;
        }
    }
}

// ---------------------------------------------------------------------------
extern "C" void kernel_launch(void* const* d_in, const int* in_sizes, int n_in,
                              void* d_out, int out_size)
{
    const float* cls = (const float*)d_in[0];
    const float* reg = (const float*)d_in[1];
    const float* anc = (const float*)d_in[2];
    const int*   ph  = (n_in > 3) ? (const int*)d_in[3] : nullptr;
    const int*   pw  = (n_in > 4) ? (const int*)d_in[4] : nullptr;

    int A = in_sizes[2] / 4;
    if (A > MAXA) A = MAXA;
    int C = in_sizes[0] / A;

    prep_kernel<<<(A + 63) / 64, 256>>>(cls, reg, anc, ph, pw, A, C);
    pair_kernel<<<PAIRB, 256>>>();
    scan0_kernel<<<1, 32>>>();
    flag_kernel<<<(A + 255) / 256, 256>>>(A);
    nms2_kernel<<<1, 1024>>>(cls, C, (float*)d_out);
}